// round 1
// baseline (speedup 1.0000x reference)
#include <cuda_runtime.h>

#define N_NODES 100000
#define N_EDGES 1600000
#define NFEAT   128
#define NHID    64
#define NCLASS  16

// Scratch (device globals — no allocation allowed in kernel_launch)
__device__ float g_h1[N_NODES * NHID];     // X @ W1
__device__ float g_agg1[N_NODES * NHID];   // scatter1 accumulator
__device__ float g_h2[N_NODES * NCLASS];   // relu(agg1) @ W2

// ---------------------------------------------------------------------------
// Zero agg1 and d_out (d_out is poisoned by the harness; agg1/out are
// atomically accumulated so they must start at 0 every launch).
// ---------------------------------------------------------------------------
__global__ void zero_kernel(float* __restrict__ out) {
    const int stride = gridDim.x * blockDim.x;
    int i = blockIdx.x * blockDim.x + threadIdx.x;
    const float4 z = make_float4(0.f, 0.f, 0.f, 0.f);
    const int n1 = N_NODES * NHID / 4;
    const int n2 = N_NODES * NCLASS / 4;
    for (int idx = i; idx < n1; idx += stride)
        reinterpret_cast<float4*>(g_agg1)[idx] = z;
    for (int idx = i; idx < n2; idx += stride)
        reinterpret_cast<float4*>(out)[idx] = z;
}

// ---------------------------------------------------------------------------
// GEMM1: g_h1[100000,64] = X[100000,128] @ W1[128,64]   (fp32)
// 64x64 block tile, K-chunks of 16, 256 threads, 4x4 microtile/thread.
// ---------------------------------------------------------------------------
__global__ __launch_bounds__(256) void gemm1_kernel(const float* __restrict__ X,
                                                    const float* __restrict__ W) {
    __shared__ float Xs[64][20];   // pad 20: float4-aligned rows, conflict-free col reads
    __shared__ float Ws[16][64];

    const int tid = threadIdx.x;
    const int m0  = blockIdx.x * 64;
    const int tx  = tid & 15;        // output-col group (4 cols)
    const int ty  = tid >> 4;        // output-row group (4 rows)

    // staging-load indices
    const int xrow  = tid >> 2;      // 0..63
    const int xcol4 = tid & 3;       // 0..3  -> cols [xcol4*4, +4) within k-chunk
    const int wrow  = tid >> 4;      // 0..15
    const int wcol4 = tid & 15;      // *4

    const int gm = m0 + xrow;
    const bool mvalid = (gm < N_NODES);

    float acc[4][4] = {};

    for (int kc = 0; kc < NFEAT; kc += 16) {
        float4 xv = make_float4(0.f, 0.f, 0.f, 0.f);
        if (mvalid)
            xv = *reinterpret_cast<const float4*>(&X[gm * NFEAT + kc + xcol4 * 4]);
        float4 wv = *reinterpret_cast<const float4*>(&W[(kc + wrow) * NHID + wcol4 * 4]);

        __syncthreads();
        *reinterpret_cast<float4*>(&Xs[xrow][xcol4 * 4]) = xv;
        *reinterpret_cast<float4*>(&Ws[wrow][wcol4 * 4]) = wv;
        __syncthreads();

#pragma unroll
        for (int k = 0; k < 16; k++) {
            float a0 = Xs[ty * 4 + 0][k];
            float a1 = Xs[ty * 4 + 1][k];
            float a2 = Xs[ty * 4 + 2][k];
            float a3 = Xs[ty * 4 + 3][k];
            float4 b = *reinterpret_cast<float4*>(&Ws[k][tx * 4]);
            acc[0][0] += a0 * b.x; acc[0][1] += a0 * b.y; acc[0][2] += a0 * b.z; acc[0][3] += a0 * b.w;
            acc[1][0] += a1 * b.x; acc[1][1] += a1 * b.y; acc[1][2] += a1 * b.z; acc[1][3] += a1 * b.w;
            acc[2][0] += a2 * b.x; acc[2][1] += a2 * b.y; acc[2][2] += a2 * b.z; acc[2][3] += a2 * b.w;
            acc[3][0] += a3 * b.x; acc[3][1] += a3 * b.y; acc[3][2] += a3 * b.z; acc[3][3] += a3 * b.w;
        }
    }

#pragma unroll
    for (int i = 0; i < 4; i++) {
        int m = m0 + ty * 4 + i;
        if (m < N_NODES)
            *reinterpret_cast<float4*>(&g_h1[m * NHID + tx * 4]) =
                make_float4(acc[i][0], acc[i][1], acc[i][2], acc[i][3]);
    }
}

// ---------------------------------------------------------------------------
// scatter1: agg1[dst] += w * h1[src]    (64 floats/edge, 16 threads x float4)
// red.global.add.v4.f32 = 16B vector reduction (sm_90+), 4x fewer atomic ops.
// ---------------------------------------------------------------------------
__global__ __launch_bounds__(256) void scatter1_kernel(const int* __restrict__ ei,
                                                       const float* __restrict__ ew) {
    int gid = blockIdx.x * blockDim.x + threadIdx.x;
    int e = gid >> 4;
    int c = gid & 15;
    if (e >= N_EDGES) return;
    int s = ei[e];
    int d = ei[N_EDGES + e];
    float w = ew[e];
    float4 v = *reinterpret_cast<const float4*>(&g_h1[s * NHID + c * 4]);
    v.x *= w; v.y *= w; v.z *= w; v.w *= w;
    float* dst = &g_agg1[d * NHID + c * 4];
    asm volatile("red.global.add.v4.f32 [%0], {%1, %2, %3, %4};"
                 :: "l"(dst), "f"(v.x), "f"(v.y), "f"(v.z), "f"(v.w)
                 : "memory");
}

// ---------------------------------------------------------------------------
// GEMM2 (+fused ReLU): g_h2[100000,16] = relu(g_agg1)[100000,64] @ W2[64,16]
// 4 threads per node, each owns 4 output cols.
// ---------------------------------------------------------------------------
__global__ __launch_bounds__(256) void gemm2_kernel(const float* __restrict__ W2) {
    __shared__ float Ws[NHID * NCLASS];  // 1024 floats, row-major [64][16]
    const int tid = threadIdx.x;
    // stage W2 (256 threads x 1 float4 = 1024 floats)
    reinterpret_cast<float4*>(Ws)[tid] = reinterpret_cast<const float4*>(W2)[tid];
    __syncthreads();

    int gid = blockIdx.x * blockDim.x + tid;
    int node = gid >> 2;
    int cg = gid & 3;        // col group: cols [cg*4, +4)
    if (node >= N_NODES) return;

    float4 acc = make_float4(0.f, 0.f, 0.f, 0.f);
#pragma unroll
    for (int k4 = 0; k4 < NHID / 4; k4++) {
        float4 a = *reinterpret_cast<const float4*>(&g_agg1[node * NHID + k4 * 4]);
        a.x = fmaxf(a.x, 0.f); a.y = fmaxf(a.y, 0.f);
        a.z = fmaxf(a.z, 0.f); a.w = fmaxf(a.w, 0.f);
#pragma unroll
        for (int j = 0; j < 4; j++) {
            float av = (j == 0) ? a.x : (j == 1) ? a.y : (j == 2) ? a.z : a.w;
            float4 wr = *reinterpret_cast<float4*>(&Ws[(k4 * 4 + j) * NCLASS + cg * 4]);
            acc.x += av * wr.x; acc.y += av * wr.y;
            acc.z += av * wr.z; acc.w += av * wr.w;
        }
    }
    *reinterpret_cast<float4*>(&g_h2[node * NCLASS + cg * 4]) = acc;
}

// ---------------------------------------------------------------------------
// scatter2: out[dst] += w * h2[src]    (16 floats/edge, 4 threads x float4)
// ---------------------------------------------------------------------------
__global__ __launch_bounds__(256) void scatter2_kernel(const int* __restrict__ ei,
                                                       const float* __restrict__ ew,
                                                       float* __restrict__ out) {
    int gid = blockIdx.x * blockDim.x + threadIdx.x;
    int e = gid >> 2;
    int c = gid & 3;
    if (e >= N_EDGES) return;
    int s = ei[e];
    int d = ei[N_EDGES + e];
    float w = ew[e];
    float4 v = *reinterpret_cast<const float4*>(&g_h2[s * NCLASS + c * 4]);
    v.x *= w; v.y *= w; v.z *= w; v.w *= w;
    float* dst = &out[d * NCLASS + c * 4];
    asm volatile("red.global.add.v4.f32 [%0], {%1, %2, %3, %4};"
                 :: "l"(dst), "f"(v.x), "f"(v.y), "f"(v.z), "f"(v.w)
                 : "memory");
}

// ---------------------------------------------------------------------------
extern "C" void kernel_launch(void* const* d_in, const int* in_sizes, int n_in,
                              void* d_out, int out_size) {
    const float* x   = (const float*)d_in[0];
    const int*   ei1 = (const int*)  d_in[1];
    const int*   ei2 = (const int*)  d_in[2];
    const float* ew1 = (const float*)d_in[3];
    const float* ew2 = (const float*)d_in[4];
    const float* W1  = (const float*)d_in[5];
    const float* W2  = (const float*)d_in[6];
    float* out = (float*)d_out;

    zero_kernel<<<2048, 256>>>(out);
    gemm1_kernel<<<(N_NODES + 63) / 64, 256>>>(x, W1);
    scatter1_kernel<<<(N_EDGES * 16 + 255) / 256, 256>>>(ei1, ew1);
    gemm2_kernel<<<(N_NODES * 4 + 255) / 256, 256>>>(W2);
    scatter2_kernel<<<(N_EDGES * 4 + 255) / 256, 256>>>(ei2, ew2, out);
}